// round 3
// baseline (speedup 1.0000x reference)
#include <cuda_runtime.h>

#define NB 16            // batch
#define NS 65            // segments per batch
#define NR 1040          // NB*NS rows
#define NW 256           // candidate positions per row
#define ND 128           // feature dim
#define T_PAD 2176       // padded time length of x
#define LSEQ 2048        // MAX_LEN_SEQ
#define MIN_SEG 32
#define NOUT (NB * LSEQ) // 32768 output rows

// Per-output-row descriptor: .x = base | (w << 16)  (base = bx*T_PAD + offset),
//                            .y = bitcast(float scale). Sentinel .x = 0xFFFFFFFF.
__device__ uint2 g_entry[NOUT];

// ---------------------------------------------------------------------------
// Fused setup: segment-offset cumsum, per-row masked count (binary search over
// the monotone prefix mask), exclusive scan, sentinel fill, and expansion of
// the compaction mapping into the output-indexed descriptor table.
// Single block, 1024 threads.
// ---------------------------------------------------------------------------
__global__ void __launch_bounds__(1024)
setup_kernel(const float* __restrict__ scales,
             const int* __restrict__ len_seq,
             const int* __restrict__ len_seg_raw) {
    __shared__ int sh_seg[NR];
    __shared__ int sh_off[NR];
    __shared__ int sh_rs[NR];      // exclusive row starts
    __shared__ int sh_sum[1024];
    __shared__ int sh_L;
    int tid = threadIdx.x;

    for (int i = tid; i < NR; i += 1024) sh_seg[i] = len_seg_raw[i] + MIN_SEG;
    __syncthreads();

    // per-batch exclusive cumsum of segment lengths (16 serial scanners)
    if (tid < NB) {
        int acc = 0, base = tid * NS;
        for (int s = 0; s < NS; s++) { sh_off[base + s] = acc; acc += sh_seg[base + s]; }
    }
    __syncthreads();

    // counts for rows 2*tid, 2*tid+1 via binary search over w.
    // mask(w) = floor(rn(w/sc)) < Tm,  Tm = min(lseg-1, lseq-1-offset); monotone.
    int a0 = 0, a1 = 0;
    #pragma unroll
    for (int e = 0; e < 2; e++) {
        int r = 2 * tid + e;
        int cnt = 0;
        if (r < NR) {
            int b = r / NS;
            int Tm = min(sh_seg[r] - 1, len_seq[b] - 1 - sh_off[r]);
            float sc = scales[r] + 0.5f;
            float fT = (float)Tm;
            int lo = 0, hi = NW;
            while (lo < hi) {
                int mid = (lo + hi) >> 1;
                float fl = floorf(__fdiv_rn((float)mid, sc));  // exact ref semantics
                if (fl >= fT) hi = mid; else lo = mid + 1;
            }
            cnt = lo;   // prefix length
        }
        if (e == 0) a0 = cnt; else a1 = cnt;
    }

    int s = a0 + a1;
    sh_sum[tid] = s;
    __syncthreads();
    #pragma unroll
    for (int off = 1; off < 1024; off <<= 1) {
        int v = (tid >= off) ? sh_sum[tid - off] : 0;
        __syncthreads();
        sh_sum[tid] += v;
        __syncthreads();
    }
    int incl = sh_sum[tid];
    int excl = incl - s;
    int i0 = 2 * tid, i1 = 2 * tid + 1;
    if (i0 < NR) sh_rs[i0] = excl;
    if (i1 < NR) sh_rs[i1] = excl + a0;
    if (tid == 1023) sh_L = incl / NB;    // incl(tid=1023) == total

    // sentinel-fill the descriptor table (overwritten below where valid)
    uint2 sent; sent.x = 0xFFFFFFFFu; sent.y = 0;
    for (int i = tid; i < NOUT; i += 1024) g_entry[i] = sent;
    __syncthreads();

    // expansion: warp per segment row, lanes cover the row's prefix run
    int L = sh_L;
    int warp = tid >> 5, lane = tid & 31;
    for (int r = warp; r < NR; r += 32) {
        int cnt = ((r + 1 < NR) ? sh_rs[r + 1]
                                : sh_rs[NR - 1] + 0) - sh_rs[r];
        // last row's cnt: recompute from totals
        if (r == NR - 1) cnt = L * NB > sh_rs[r] ? 0 : 0;  // placeholder (fixed below)
        // NOTE: we recompute cnt robustly below instead
        cnt = (r + 1 < NR ? sh_rs[r + 1] : (sh_sum[1023])) - sh_rs[r];
        if (cnt == 0) continue;
        int g0   = sh_rs[r];
        int bx   = r / NS;
        int base = bx * T_PAD + sh_off[r];
        float sc = scales[r] + 0.5f;
        uint2 ev; ev.y = __float_as_uint(sc);
        for (int k = lane; k < cnt; k += 32) {
            int g = g0 + k;
            int bo = g / L;
            int t  = g - bo * L;
            if (bo < NB && t < LSEQ) {
                ev.x = (unsigned)base | ((unsigned)k << 16);
                g_entry[bo * LSEQ + t] = ev;
            }
        }
    }
}

// ---------------------------------------------------------------------------
// Gather: one warp per output row. Single descriptor load, then lerp two
// contiguous source rows of x. PDL-synced against setup.
// ---------------------------------------------------------------------------
__global__ void __launch_bounds__(256)
gather_kernel(const float* __restrict__ x, float* __restrict__ out) {
#if __CUDA_ARCH__ >= 900
    cudaGridDependencySynchronize();   // PDL: wait for setup_kernel results
#endif
    int gid  = (blockIdx.x * blockDim.x + threadIdx.x) >> 5;  // output row id
    int lane = threadIdx.x & 31;
    if (gid >= NOUT) return;

    uint2 e = __ldg(&g_entry[gid]);
    float4* orow = (float4*)(out + (size_t)gid * ND);
    if (e.x == 0xFFFFFFFFu) {
        orow[lane] = make_float4(0.f, 0.f, 0.f, 0.f);
        return;
    }
    int base = (int)(e.x & 0xFFFFu);
    int w    = (int)(e.x >> 16);
    float sc = __uint_as_float(e.y);

    float fs = __fdiv_rn((float)w, sc);
    float fl = floorf(fs);
    float lam = fs - fl;
    int i0 = base + (int)fl;          // masked entries never need clamping

    const float4* p0 = (const float4*)(x + (size_t)i0 * ND);
    float4 a = p0[lane];              // row i0
    float4 c = p0[lane + 32];         // row i0+1 (contiguous)
    float om = 1.0f - lam;
    float4 y;
    y.x = om * a.x + lam * c.x;
    y.y = om * a.y + lam * c.y;
    y.z = om * a.z + lam * c.z;
    y.w = om * a.w + lam * c.w;
    orow[lane] = y;
}

extern "C" void kernel_launch(void* const* d_in, const int* in_sizes, int n_in,
                              void* d_out, int out_size) {
    const float* x           = (const float*)d_in[0];
    const float* scales      = (const float*)d_in[1];
    const int*   len_seq     = (const int*)d_in[2];
    const int*   len_seg_raw = (const int*)d_in[3];
    float* out = (float*)d_out;

    setup_kernel<<<1, 1024>>>(scales, len_seq, len_seg_raw);

    cudaLaunchConfig_t cfg = {};
    cfg.gridDim  = dim3((NOUT * 32) / 256);
    cfg.blockDim = dim3(256);
    cfg.dynamicSmemBytes = 0;
    cfg.stream = 0;
    cudaLaunchAttribute attr[1];
    attr[0].id = cudaLaunchAttributeProgrammaticStreamSerialization;
    attr[0].val.programmaticStreamSerializationAllowed = 1;
    cfg.attrs = attr;
    cfg.numAttrs = 1;
    cudaLaunchKernelEx(&cfg, gather_kernel, x, out);
}

// round 4
// speedup vs baseline: 2.1186x; 2.1186x over previous
#include <cuda_runtime.h>

#define NB 16            // batch
#define NS 65            // segments per batch
#define NR 1040          // NB*NS rows
#define NW 256           // candidate positions per row
#define ND 128           // feature dim
#define T_PAD 2176       // padded time length of x
#define LSEQ 2048        // MAX_LEN_SEQ
#define MIN_SEG 32
#define NOUT (NB * LSEQ) // 32768 output rows
#define SENT 0xFFFFFFFFu

#define EXP_BLOCKS 130   // warp-per-row expansion blocks
#define FILL_BLOCKS 30   // sentinel-fill blocks

__device__ int  g_rowstart[NR + 1];
__device__ int  g_offset[NR];
__device__ int  g_L[1];
// Per-output-row descriptor: .x = base | (w<<16)  (base = bx*T_PAD + offset < 2^16),
//                            .y = bitcast(float scale). Sentinel .x = SENT.
__device__ uint2 g_entry[NOUT];

// ---------------------------------------------------------------------------
// Kernel A: per-batch segment-offset cumsum, per-row masked count via binary
// search (mask is a monotone prefix in w, exact fp32 ref semantics), and
// block-wide exclusive scan. Single block, 1024 threads.
// ---------------------------------------------------------------------------
__global__ void __launch_bounds__(1024)
setup_kernel(const float* __restrict__ scales,
             const int* __restrict__ len_seq,
             const int* __restrict__ len_seg_raw) {
    __shared__ int sh_seg[NR];
    __shared__ int sh_off[NR];
    __shared__ int sh_sum[1024];
    int tid = threadIdx.x;

    for (int i = tid; i < NR; i += 1024) sh_seg[i] = len_seg_raw[i] + MIN_SEG;
    __syncthreads();

    if (tid < NB) {           // 16 serial per-batch scanners
        int acc = 0, base = tid * NS;
        for (int s = 0; s < NS; s++) { sh_off[base + s] = acc; acc += sh_seg[base + s]; }
    }
    __syncthreads();

    // counts for rows 2*tid, 2*tid+1:  mask(w) = floor(rn(w/sc)) < Tm, monotone
    int a0 = 0, a1 = 0;
    #pragma unroll
    for (int e = 0; e < 2; e++) {
        int r = 2 * tid + e;
        int cnt = 0;
        if (r < NR) {
            int b = r / NS;
            int Tm = min(sh_seg[r] - 1, len_seq[b] - 1 - sh_off[r]);
            float sc = scales[r] + 0.5f;
            float fT = (float)Tm;
            int lo = 0, hi = NW;
            while (lo < hi) {
                int mid = (lo + hi) >> 1;
                float fl = floorf(__fdiv_rn((float)mid, sc));  // exact ref semantics
                if (fl >= fT) hi = mid; else lo = mid + 1;
            }
            cnt = lo;
        }
        if (e == 0) a0 = cnt; else a1 = cnt;
    }

    int s = a0 + a1;
    sh_sum[tid] = s;
    __syncthreads();
    #pragma unroll
    for (int off = 1; off < 1024; off <<= 1) {
        int v = (tid >= off) ? sh_sum[tid - off] : 0;
        __syncthreads();
        sh_sum[tid] += v;
        __syncthreads();
    }
    int incl = sh_sum[tid];
    int excl = incl - s;
    int i0 = 2 * tid, i1 = 2 * tid + 1;
    if (i0 < NR) { g_rowstart[i0] = excl;      g_offset[i0] = sh_off[i0]; }
    if (i1 < NR) { g_rowstart[i1] = excl + a0; g_offset[i1] = sh_off[i1]; }
    if (tid == 1023) {
        g_rowstart[NR] = incl;       // total masked count
        g_L[0] = incl / NB;
    }
}

// ---------------------------------------------------------------------------
// Kernel B: grid-wide table build. Blocks [0,130): warp-per-segment-row run
// expansion. Blocks [130,160): sentinel fill for t >= L (disjoint entries).
// ---------------------------------------------------------------------------
__global__ void __launch_bounds__(256)
expand_kernel(const float* __restrict__ scales) {
#if __CUDA_ARCH__ >= 900
    cudaGridDependencySynchronize();
#endif
    int L = g_L[0];
    if (blockIdx.x < EXP_BLOCKS) {
        int r = (blockIdx.x * 256 + threadIdx.x) >> 5;   // one warp per row
        int lane = threadIdx.x & 31;
        if (r >= NR) return;
        int g0  = g_rowstart[r];
        int cnt = g_rowstart[r + 1] - g0;
        if (cnt == 0) return;
        int base = (r / NS) * T_PAD + g_offset[r];
        uint2 ev;
        ev.y = __float_as_uint(scales[r] + 0.5f);
        for (int k = lane; k < cnt; k += 32) {
            int g  = g0 + k;
            int bo = g / L;
            int t  = g - bo * L;
            if (bo < NB && t < LSEQ) {
                ev.x = (unsigned)base | ((unsigned)k << 16);
                g_entry[bo * LSEQ + t] = ev;
            }
        }
    } else {
        // sentinel fill for zero rows (t >= L); no-op when L >= LSEQ
        uint2 sent; sent.x = SENT; sent.y = 0;
        int i0 = (blockIdx.x - EXP_BLOCKS) * 256 + threadIdx.x;
        for (int i = i0; i < NOUT; i += FILL_BLOCKS * 256) {
            int t = i & (LSEQ - 1);
            if (t >= L) g_entry[i] = sent;
        }
    }
}

// ---------------------------------------------------------------------------
// Kernel C: gather. Two output rows per warp; both descriptors come from one
// 16B load; four independent 512B row loads in flight before the lerp.
// ---------------------------------------------------------------------------
__global__ void __launch_bounds__(256)
gather_kernel(const float* __restrict__ x, float* __restrict__ out) {
#if __CUDA_ARCH__ >= 900
    cudaGridDependencySynchronize();
#endif
    int warp = (blockIdx.x * blockDim.x + threadIdx.x) >> 5;
    int lane = threadIdx.x & 31;
    int gid0 = warp << 1;              // even => 16B-aligned pair in g_entry
    if (gid0 >= NOUT) return;

    uint4 ee = __ldg((const uint4*)(g_entry + gid0));
    bool v0 = (ee.x != SENT);
    bool v1 = (ee.z != SENT);

    float4 a0, c0, a1, c1;
    float lam0 = 0.f, lam1 = 0.f;
    if (v0) {
        int base = (int)(ee.x & 0xFFFFu), w = (int)(ee.x >> 16);
        float fs = __fdiv_rn((float)w, __uint_as_float(ee.y));
        float fl = floorf(fs); lam0 = fs - fl;
        const float4* p = (const float4*)(x + (size_t)(base + (int)fl) * ND);
        a0 = p[lane]; c0 = p[lane + 32];
    }
    if (v1) {
        int base = (int)(ee.z & 0xFFFFu), w = (int)(ee.z >> 16);
        float fs = __fdiv_rn((float)w, __uint_as_float(ee.w));
        float fl = floorf(fs); lam1 = fs - fl;
        const float4* p = (const float4*)(x + (size_t)(base + (int)fl) * ND);
        a1 = p[lane]; c1 = p[lane + 32];
    }

    float4 y0 = make_float4(0.f, 0.f, 0.f, 0.f);
    float4 y1 = y0;
    if (v0) {
        float om = 1.0f - lam0;
        y0.x = om * a0.x + lam0 * c0.x;  y0.y = om * a0.y + lam0 * c0.y;
        y0.z = om * a0.z + lam0 * c0.z;  y0.w = om * a0.w + lam0 * c0.w;
    }
    if (v1) {
        float om = 1.0f - lam1;
        y1.x = om * a1.x + lam1 * c1.x;  y1.y = om * a1.y + lam1 * c1.y;
        y1.z = om * a1.z + lam1 * c1.z;  y1.w = om * a1.w + lam1 * c1.w;
    }
    ((float4*)(out + (size_t)gid0 * ND))[lane]       = y0;
    ((float4*)(out + (size_t)(gid0 + 1) * ND))[lane] = y1;
}

static inline void launch_pdl(void* fn, dim3 grid, dim3 block,
                              void** args) {
    cudaLaunchConfig_t cfg = {};
    cfg.gridDim = grid;
    cfg.blockDim = block;
    cfg.dynamicSmemBytes = 0;
    cfg.stream = 0;
    cudaLaunchAttribute attr[1];
    attr[0].id = cudaLaunchAttributeProgrammaticStreamSerialization;
    attr[0].val.programmaticStreamSerializationAllowed = 1;
    cfg.attrs = attr;
    cfg.numAttrs = 1;
    cudaLaunchKernelExC(&cfg, fn, args);
}

extern "C" void kernel_launch(void* const* d_in, const int* in_sizes, int n_in,
                              void* d_out, int out_size) {
    const float* x           = (const float*)d_in[0];
    const float* scales      = (const float*)d_in[1];
    const int*   len_seq     = (const int*)d_in[2];
    const int*   len_seg_raw = (const int*)d_in[3];
    float* out = (float*)d_out;

    setup_kernel<<<1, 1024>>>(scales, len_seq, len_seg_raw);

    {   // expand (PDL after setup)
        void* args[] = { (void*)&scales };
        launch_pdl((void*)expand_kernel,
                   dim3(EXP_BLOCKS + FILL_BLOCKS), dim3(256), args);
    }
    {   // gather (PDL after expand): NOUT/2 warps, 8 warps/block
        void* args[] = { (void*)&x, (void*)&out };
        launch_pdl((void*)gather_kernel,
                   dim3(NOUT / 2 / 8), dim3(256), args);
    }
}